// round 14
// baseline (speedup 1.0000x reference)
#include <cuda_runtime.h>

// Fixed shapes: x = (4,64,256,256) f32, stoken = 16
#define Bn 4
#define Cc 64
#define NH 16      // superpixel grid 16x16
#define NS 256     // nH*nW
#define PP 65536   // H*W

typedef unsigned long long ull;

// Scratch (allocation-free: __device__ globals)
__device__ float g_cent[Bn * NS * Cc];
__device__ float g_num [Bn * NS * Cc];
__device__ float g_den [Bn * NS];

__device__ __forceinline__ void ffma2(ull& acc, ull a, ull b) {
    asm("fma.rn.f32x2 %0, %1, %2, %0;" : "+l"(acc) : "l"(a), "l"(b));
}
__device__ __forceinline__ ull pack2(float x, float y) {
    ull r; asm("mov.b64 %0, {%1, %2};" : "=l"(r) : "f"(x), "f"(y)); return r;
}
__device__ __forceinline__ float2 unpack2(ull v) {
    float2 r; asm("mov.b64 {%0, %1}, %2;" : "=f"(r.x), "=f"(r.y) : "l"(v)); return r;
}

// ---------------------------------------------------------------------------
// Inline zero-fill of a slice [lo,hi) of plane (b,s), skipping float4s inside
// the plane's 3x3 affinity region (written by pass 1's scatter — byte-disjoint,
// no ordering needed). Fire-and-forget streaming stores.
// ---------------------------------------------------------------------------
template <int NT>
__device__ __forceinline__ void fill_slice(float4* __restrict__ A, int b, int s,
                                           int lo, int hi, int tid) {
    int si = s >> 4, sj = s & 15;
    float4* plane = A + ((size_t)(b * NS + s) << 14);   // 16384 float4 per plane
    const float4 z = make_float4(0.f, 0.f, 0.f, 0.f);
    #pragma unroll 4
    for (int e4 = lo + tid; e4 < hi; e4 += NT) {
        int p = e4 << 2;
        int bi = p >> 12;
        int bj = (p >> 4) & 15;
        int di = si - bi + 1, dj = sj - bj + 1;
        if ((unsigned)di > 2u || (unsigned)dj > 2u)
            __stcs(&plane[e4], z);
    }
}

// Fill split across the three chain kernels (16384 float4 per plane total).
#define FILL_INIT_END 3584
#define FILL_P0_END   9984

// ---------------------------------------------------------------------------
// Initial centroids: block mean over each 16x16 block. Also zeroes scratch
// and fills its plane slice [0, FILL_INIT_END).  (unchanged from r13)
// ---------------------------------------------------------------------------
__global__ __launch_bounds__(256) void init_cent_kernel(const float* __restrict__ x,
                                                        float4* __restrict__ A) {
    int b = blockIdx.y, s = blockIdx.x;
    int bi = s >> 4, bj = s & 15;
    int tid = threadIdx.x;

    fill_slice<256>(A, b, s, 0, FILL_INIT_END, tid);

    int c = tid >> 2, q = tid & 3;
    int base = ((bi * 16) << 8) + bj * 16;
    const float4* fc = (const float4*)(x + (((size_t)b * Cc + c) << 16) + base);
    float4 s4 = make_float4(0.f, 0.f, 0.f, 0.f);
    #pragma unroll
    for (int t = 0; t < 16; t++) {
        int j = q + t * 4;
        float4 v = fc[(j >> 2) * 64 + (j & 3)];
        s4.x += v.x; s4.y += v.y; s4.z += v.z; s4.w += v.w;
    }
    float acc = (s4.x + s4.y) + (s4.z + s4.w);
    __shared__ float part[256];
    part[tid] = acc;
    __syncthreads();
    if (tid < 64) {
        int o4 = tid * 4;
        float v = (part[o4] + part[o4 + 1]) + (part[o4 + 2] + part[o4 + 3]);
        int idx = (b * NS + s) * Cc + tid;
        g_cent[idx] = v * (1.f / 256.f);
        g_num[idx]  = 0.f;
    }
    if (tid == 64) g_den[b * NS + s] = 0.f;
}

// ---------------------------------------------------------------------------
// Affinity pass. CTA = 128 threads = one 16x16 block; each thread owns 2
// ADJACENT pixels: all x accesses are LDG.64, all f32x2 accumulators carry
// (pixel0, pixel1). Centroids staged duplicated: cent2_sm[k][c] = (-2c, -2c).
// Softmax shift-invariance drops f2: logit = -(0.25*sum(t^2) + sum(f*t)).
// Dot phase batches 16 channel LDG.64s per iteration (2x in-flight vs r13).
// PASS 0: fused num/den reduction (pair loads + partner-shuffle atomics).
// PASS 1: direct STG.64 scatter from registers.
// ---------------------------------------------------------------------------
template <int PASS>
__global__ __launch_bounds__(128) void affinity_kernel(const float* __restrict__ x,
                                                       float* __restrict__ A) {
    int b = blockIdx.y, sblk = blockIdx.x;
    int bi = sblk >> 4, bj = sblk & 15;
    int tid = threadIdx.x;

    __shared__ __align__(16) ull cent2_sm[9][64];   // (-2c, -2c) per channel
    __shared__ ull   aff_sm[9][128];                // pair-packed (pass0 only)
    __shared__ float c2_sm[9];
    __shared__ float den_sm[9];
    __shared__ int   cand_s[9];
    __shared__ int   cand_v[9];
    __shared__ float denpart[4][9];

    if (tid < 9) {
        int ci = bi + tid / 3 - 1, cj = bj + tid % 3 - 1;
        int v = (ci >= 0 && ci < NH && cj >= 0 && cj < NH);
        cand_v[tid] = v;
        int s = v ? ci * NH + cj : 0;
        cand_s[tid] = s;
        if (PASS == 1) den_sm[tid] = g_den[b * NS + s] + 1e-16f;
    }

    // streamed zero-fill of this CTA's plane slice (overlaps with compute)
    if (PASS == 0) fill_slice<128>((float4*)A, b, sblk, FILL_INIT_END, FILL_P0_END, tid);
    else           fill_slice<128>((float4*)A, b, sblk, FILL_P0_END, 16384, tid);

    __syncthreads();
    for (int i = tid; i < 9 * 64; i += 128) {
        int k = i >> 6, c = i & 63;
        int gi = (b * NS + cand_s[k]) * Cc + c;
        float cv = (PASS == 0) ? g_cent[gi] : g_num[gi] / den_sm[k];
        float t2 = -2.f * cv;
        cent2_sm[k][c] = pack2(t2, t2);
    }
    __syncthreads();
    if (tid < 9) {
        float s2 = 0.f;
        #pragma unroll 8
        for (int c = 0; c < 64; c++) {
            float2 h = unpack2(cent2_sm[tid][c]);
            s2 += h.x * h.x;
        }
        c2_sm[tid] = 0.25f * s2;
    }
    __syncthreads();

    // ---- dot phase: pixel pair per thread, 16-channel LDG.64 batches ----
    int row = tid >> 3, cp = tid & 7;
    int p0 = ((bi * 16 + row) << 8) + bj * 16 + (cp << 1);   // first of pair
    const float* fb = x + (((size_t)b * Cc) << 16) + p0;
    ull dacc[9];
    #pragma unroll
    for (int k = 0; k < 9; k++) dacc[k] = 0ull;
    #pragma unroll
    for (int cc = 0; cc < 64; cc += 16) {
        ull f[16];
        #pragma unroll
        for (int j = 0; j < 16; j++)
            f[j] = *(const ull*)(fb + ((size_t)(cc + j) << 16));
        #pragma unroll
        for (int j = 0; j < 16; j += 2) {
            #pragma unroll
            for (int k = 0; k < 9; k++) {
                ulonglong2 cv = *(const ulonglong2*)&cent2_sm[k][cc + j];
                ffma2(dacc[k], f[j],     cv.x);
                ffma2(dacc[k], f[j + 1], cv.y);
            }
        }
    }

    // ---- masked softmax for both pixels ----
    float a0[9], a1[9];
    #pragma unroll
    for (int k = 0; k < 9; k++) {
        float2 dh = unpack2(dacc[k]);
        float cb = c2_sm[k];
        bool v = cand_v[k] != 0;
        a0[k] = v ? -(cb + dh.x) : -1e30f;
        a1[k] = v ? -(cb + dh.y) : -1e30f;
    }
    #define SOFTMAX9(a) do {                                                \
        float mx = -3.0e38f;                                                \
        _Pragma("unroll") for (int k = 0; k < 9; k++) mx = fmaxf(mx, a[k]); \
        float ss = 0.f;                                                     \
        _Pragma("unroll") for (int k = 0; k < 9; k++) { a[k] = __expf(a[k] - mx); ss += a[k]; } \
        float rs = 1.f / ss;                                                \
        _Pragma("unroll") for (int k = 0; k < 9; k++) a[k] *= rs;           \
    } while (0)
    SOFTMAX9(a0); SOFTMAX9(a1);
    #pragma unroll
    for (int k = 0; k < 9; k++)
        if (!cand_v[k]) { a0[k] = 0.f; a1[k] = 0.f; }

    if (PASS == 0) {
        // stash pair-packed affinities + den warp partials
        float ds[9];
        #pragma unroll
        for (int k = 0; k < 9; k++) {
            aff_sm[k][tid] = pack2(a0[k], a1[k]);
            ds[k] = a0[k] + a1[k];
        }
        #pragma unroll
        for (int k = 0; k < 9; k++) {
            float v = ds[k];
            v += __shfl_xor_sync(0xffffffffu, v, 16);
            v += __shfl_xor_sync(0xffffffffu, v, 8);
            v += __shfl_xor_sync(0xffffffffu, v, 4);
            v += __shfl_xor_sync(0xffffffffu, v, 2);
            v += __shfl_xor_sync(0xffffffffu, v, 1);
            if ((tid & 31) == 0) denpart[tid >> 5][k] = v;
        }
        __syncthreads();

        // num[k][c] = sum_p aff[k][p]*x[c][p]: thread = (channel, half)
        int c = tid >> 1, g = tid & 1;
        const float* fc = x + (((size_t)(b * Cc + c)) << 16);
        int base = ((bi * 16) << 8) + bj * 16;
        ull acc[9];
        #pragma unroll
        for (int k = 0; k < 9; k++) acc[k] = 0ull;
        #pragma unroll 4
        for (int t = 0; t < 64; t++) {
            int q = t * 2 + g;                         // pair index 0..127
            int r = q >> 3, cpq = q & 7;
            ull fp = *(const ull*)(fc + base + (r << 8) + (cpq << 1));
            #pragma unroll
            for (int k = 0; k < 9; k++)
                ffma2(acc[k], fp, aff_sm[k][q]);
        }
        #pragma unroll
        for (int k = 0; k < 9; k++) {
            float2 h = unpack2(acc[k]);
            float v = h.x + h.y;
            v += __shfl_xor_sync(0xffffffffu, v, 1);   // partner (g=0/1) merge
            if (g == 0 && cand_v[k])
                atomicAdd(&g_num[(b * NS + cand_s[k]) * Cc + c], v);
        }
        if (tid < 9 && cand_v[tid]) {
            float v = (denpart[0][tid] + denpart[1][tid])
                    + (denpart[2][tid] + denpart[3][tid]);
            atomicAdd(&g_den[b * NS + cand_s[tid]], v);
        }
    } else {
        // scatter: pixel pair = one STG.64 per candidate, straight from regs
        #pragma unroll
        for (int k = 0; k < 9; k++) {
            if (cand_v[k]) {
                size_t off = (((size_t)(b * NS + cand_s[k])) << 16) + p0;
                __stcs((float2*)(A + off), make_float2(a0[k], a1[k]));
            }
        }
    }
}

extern "C" void kernel_launch(void* const* d_in, const int* in_sizes, int n_in,
                              void* d_out, int out_size) {
    const float* x = (const float*)d_in[0];
    float* A = (float*)d_out;

    dim3 grid(NS, Bn);
    // Single stream; zero-fill is folded into each kernel as streaming stores.
    init_cent_kernel<<<grid, 256>>>(x, (float4*)A);
    affinity_kernel<0><<<grid, 128>>>(x, A);
    affinity_kernel<1><<<grid, 128>>>(x, A);
}

// round 16
// speedup vs baseline: 1.1089x; 1.1089x over previous
#include <cuda_runtime.h>

// Fixed shapes: x = (4,64,256,256) f32, stoken = 16
#define Bn 4
#define Cc 64
#define NH 16      // superpixel grid 16x16
#define NS 256     // nH*nW
#define PP 65536   // H*W

typedef unsigned long long ull;

// Scratch (allocation-free: __device__ globals)
__device__ float g_cent[Bn * NS * Cc];
__device__ float g_num [Bn * NS * Cc];
__device__ float g_den [Bn * NS];

__device__ __forceinline__ void ffma2(ull& acc, ull a, ull b) {
    asm("fma.rn.f32x2 %0, %1, %2, %0;" : "+l"(acc) : "l"(a), "l"(b));
}
__device__ __forceinline__ ull pack2(float x, float y) {
    ull r; asm("mov.b64 %0, {%1, %2};" : "=l"(r) : "f"(x), "f"(y)); return r;
}
__device__ __forceinline__ float2 unpack2(ull v) {
    float2 r; asm("mov.b64 {%0, %1}, %2;" : "=f"(r.x), "=f"(r.y) : "l"(v)); return r;
}

// ---------------------------------------------------------------------------
// Inline zero-fill of a slice [lo,hi) of plane (b,s), skipping float4s inside
// the plane's 3x3 affinity region (written by pass 1's scatter — byte-disjoint,
// no ordering needed). Fire-and-forget streaming stores.
// ---------------------------------------------------------------------------
template <int NT>
__device__ __forceinline__ void fill_slice(float4* __restrict__ A, int b, int s,
                                           int lo, int hi, int tid) {
    int si = s >> 4, sj = s & 15;
    float4* plane = A + ((size_t)(b * NS + s) << 14);   // 16384 float4 per plane
    const float4 z = make_float4(0.f, 0.f, 0.f, 0.f);
    #pragma unroll 4
    for (int e4 = lo + tid; e4 < hi; e4 += NT) {
        int p = e4 << 2;
        int bi = p >> 12;
        int bj = (p >> 4) & 15;
        int di = si - bi + 1, dj = sj - bj + 1;
        if ((unsigned)di > 2u || (unsigned)dj > 2u)
            __stcs(&plane[e4], z);
    }
}

// Fill split across the three chain kernels (16384 float4 per plane total).
#define FILL_INIT_END 3584
#define FILL_P0_END   9984

// ---------------------------------------------------------------------------
// Initial centroids: block mean over each 16x16 block. Also zeroes scratch
// and fills its plane slice [0, FILL_INIT_END).  (unchanged from r13)
// ---------------------------------------------------------------------------
__global__ __launch_bounds__(256) void init_cent_kernel(const float* __restrict__ x,
                                                        float4* __restrict__ A) {
    int b = blockIdx.y, s = blockIdx.x;
    int bi = s >> 4, bj = s & 15;
    int tid = threadIdx.x;

    fill_slice<256>(A, b, s, 0, FILL_INIT_END, tid);

    int c = tid >> 2, q = tid & 3;
    int base = ((bi * 16) << 8) + bj * 16;
    const float4* fc = (const float4*)(x + (((size_t)b * Cc + c) << 16) + base);
    float4 s4 = make_float4(0.f, 0.f, 0.f, 0.f);
    #pragma unroll
    for (int t = 0; t < 16; t++) {
        int j = q + t * 4;
        float4 v = fc[(j >> 2) * 64 + (j & 3)];
        s4.x += v.x; s4.y += v.y; s4.z += v.z; s4.w += v.w;
    }
    float acc = (s4.x + s4.y) + (s4.z + s4.w);
    __shared__ float part[256];
    part[tid] = acc;
    __syncthreads();
    if (tid < 64) {
        int o4 = tid * 4;
        float v = (part[o4] + part[o4 + 1]) + (part[o4 + 2] + part[o4 + 3]);
        int idx = (b * NS + s) * Cc + tid;
        g_cent[idx] = v * (1.f / 256.f);
        g_num[idx]  = 0.f;
    }
    if (tid == 64) g_den[b * NS + s] = 0.f;
}

// ---------------------------------------------------------------------------
// Affinity pass. CTA = 128 threads = one 16x16 block; each thread owns 2
// ADJACENT pixels: all x accesses are LDG.64/LDG.128, all f32x2 accumulators
// carry (pixel0, pixel1). Centroids staged duplicated: cent2_sm[k][c]=(-2c,-2c).
// Softmax shift-invariance drops f2: logit = -(0.25*sum(t^2) + sum(f*t)).
// PASS 0: fused num/den reduction (LDG.128 quads + partner-shuffle atomics).
// PASS 1: direct STG.64 scatter from registers.
// ---------------------------------------------------------------------------
template <int PASS>
__global__ __launch_bounds__(128) void affinity_kernel(const float* __restrict__ x,
                                                       float* __restrict__ A) {
    int b = blockIdx.y, sblk = blockIdx.x;
    int bi = sblk >> 4, bj = sblk & 15;
    int tid = threadIdx.x;

    __shared__ __align__(16) ull cent2_sm[9][64];   // (-2c, -2c) per channel
    __shared__ __align__(16) ull aff_sm[9][128];    // pair-packed (pass0 only)
    __shared__ float c2_sm[9];
    __shared__ float c2part[9][8];
    __shared__ float den_sm[9];
    __shared__ int   cand_s[9];
    __shared__ int   cand_v[9];
    __shared__ float denpart[4][9];

    if (tid < 9) {
        int ci = bi + tid / 3 - 1, cj = bj + tid % 3 - 1;
        int v = (ci >= 0 && ci < NH && cj >= 0 && cj < NH);
        cand_v[tid] = v;
        int s = v ? ci * NH + cj : 0;
        cand_s[tid] = s;
        if (PASS == 1) den_sm[tid] = g_den[b * NS + s] + 1e-16f;
    }

    // streamed zero-fill of this CTA's plane slice (overlaps with compute)
    if (PASS == 0) fill_slice<128>((float4*)A, b, sblk, FILL_INIT_END, FILL_P0_END, tid);
    else           fill_slice<128>((float4*)A, b, sblk, FILL_P0_END, 16384, tid);

    __syncthreads();
    for (int i = tid; i < 9 * 64; i += 128) {
        int k = i >> 6, c = i & 63;
        int gi = (b * NS + cand_s[k]) * Cc + c;
        float cv = (PASS == 0) ? g_cent[gi] : g_num[gi] / den_sm[k];
        float t2 = -2.f * cv;
        cent2_sm[k][c] = pack2(t2, t2);
    }
    __syncthreads();
    // c2 = 0.25 * sum(t^2), parallel over 72 threads then 9-way combine
    if (tid < 72) {
        int k = tid >> 3, c0 = (tid & 7) << 3;
        float s2 = 0.f;
        #pragma unroll
        for (int c = 0; c < 8; c++) {
            float2 h = unpack2(cent2_sm[k][c0 + c]);
            s2 = fmaf(h.x, h.x, s2);
        }
        c2part[k][tid & 7] = s2;
    }
    __syncthreads();
    if (tid < 9) {
        float s = 0.f;
        #pragma unroll
        for (int w = 0; w < 8; w++) s += c2part[tid][w];
        c2_sm[tid] = 0.25f * s;
    }
    __syncthreads();

    // ---- dot phase: pixel pair per thread, 8-channel LDG.64 batches ----
    int row = tid >> 3, cp = tid & 7;
    int p0 = ((bi * 16 + row) << 8) + bj * 16 + (cp << 1);   // first of pair
    const float* fb = x + (((size_t)b * Cc) << 16) + p0;
    ull dacc[9];
    #pragma unroll
    for (int k = 0; k < 9; k++) dacc[k] = 0ull;
    #pragma unroll
    for (int cc = 0; cc < 64; cc += 8) {
        ull f[8];
        #pragma unroll
        for (int j = 0; j < 8; j++)
            f[j] = *(const ull*)(fb + ((size_t)(cc + j) << 16));
        #pragma unroll
        for (int j = 0; j < 8; j += 2) {
            #pragma unroll
            for (int k = 0; k < 9; k++) {
                ulonglong2 cv = *(const ulonglong2*)&cent2_sm[k][cc + j];
                ffma2(dacc[k], f[j],     cv.x);
                ffma2(dacc[k], f[j + 1], cv.y);
            }
        }
    }

    // ---- masked softmax for both pixels ----
    float a0[9], a1[9];
    #pragma unroll
    for (int k = 0; k < 9; k++) {
        float2 dh = unpack2(dacc[k]);
        float cb = c2_sm[k];
        bool v = cand_v[k] != 0;
        a0[k] = v ? -(cb + dh.x) : -1e30f;
        a1[k] = v ? -(cb + dh.y) : -1e30f;
    }
    #define SOFTMAX9(a) do {                                                \
        float mx = -3.0e38f;                                                \
        _Pragma("unroll") for (int k = 0; k < 9; k++) mx = fmaxf(mx, a[k]); \
        float ss = 0.f;                                                     \
        _Pragma("unroll") for (int k = 0; k < 9; k++) { a[k] = __expf(a[k] - mx); ss += a[k]; } \
        float rs = 1.f / ss;                                                \
        _Pragma("unroll") for (int k = 0; k < 9; k++) a[k] *= rs;           \
    } while (0)
    SOFTMAX9(a0); SOFTMAX9(a1);
    #pragma unroll
    for (int k = 0; k < 9; k++)
        if (!cand_v[k]) { a0[k] = 0.f; a1[k] = 0.f; }

    if (PASS == 0) {
        // stash pair-packed affinities + den warp partials
        float ds[9];
        #pragma unroll
        for (int k = 0; k < 9; k++) {
            aff_sm[k][tid] = pack2(a0[k], a1[k]);
            ds[k] = a0[k] + a1[k];
        }
        #pragma unroll
        for (int k = 0; k < 9; k++) {
            float v = ds[k];
            v += __shfl_xor_sync(0xffffffffu, v, 16);
            v += __shfl_xor_sync(0xffffffffu, v, 8);
            v += __shfl_xor_sync(0xffffffffu, v, 4);
            v += __shfl_xor_sync(0xffffffffu, v, 2);
            v += __shfl_xor_sync(0xffffffffu, v, 1);
            if ((tid & 31) == 0) denpart[tid >> 5][k] = v;
        }
        __syncthreads();

        // num[k][c] = sum_p aff[k][p]*x[c][p]: thread = (channel, half),
        // pixel-QUAD LDG.128 + LDS.128; g=0/1 cover even/odd quads (all 64)
        int c = tid >> 1, g = tid & 1;
        const float* fc = x + (((size_t)(b * Cc + c)) << 16);
        int base = ((bi * 16) << 8) + bj * 16;
        ull acc[9];
        #pragma unroll
        for (int k = 0; k < 9; k++) acc[k] = 0ull;
        #pragma unroll 4
        for (int t = 0; t < 32; t++) {
            int j = t * 2 + g;                         // quad index 0..63
            int r = j >> 2, c4 = j & 3;
            float4 fq = *(const float4*)(fc + base + (r << 8) + c4 * 4);
            ull u01 = pack2(fq.x, fq.y), u23 = pack2(fq.z, fq.w);
            #pragma unroll
            for (int k = 0; k < 9; k++) {
                ulonglong2 aq = *(const ulonglong2*)&aff_sm[k][j * 2];
                ffma2(acc[k], u01, aq.x);
                ffma2(acc[k], u23, aq.y);
            }
        }
        #pragma unroll
        for (int k = 0; k < 9; k++) {
            float2 h = unpack2(acc[k]);
            float v = h.x + h.y;
            v += __shfl_xor_sync(0xffffffffu, v, 1);   // partner (g=0/1) merge
            if (g == 0 && cand_v[k])
                atomicAdd(&g_num[(b * NS + cand_s[k]) * Cc + c], v);
        }
        if (tid < 9 && cand_v[tid]) {
            float v = (denpart[0][tid] + denpart[1][tid])
                    + (denpart[2][tid] + denpart[3][tid]);
            atomicAdd(&g_den[b * NS + cand_s[tid]], v);
        }
    } else {
        // scatter: pixel pair = one STG.64 per candidate, straight from regs
        #pragma unroll
        for (int k = 0; k < 9; k++) {
            if (cand_v[k]) {
                size_t off = (((size_t)(b * NS + cand_s[k])) << 16) + p0;
                __stcs((float2*)(A + off), make_float2(a0[k], a1[k]));
            }
        }
    }
}

extern "C" void kernel_launch(void* const* d_in, const int* in_sizes, int n_in,
                              void* d_out, int out_size) {
    const float* x = (const float*)d_in[0];
    float* A = (float*)d_out;

    dim3 grid(NS, Bn);
    // Single stream; zero-fill is folded into each kernel as streaming stores.
    init_cent_kernel<<<grid, 256>>>(x, (float4*)A);
    affinity_kernel<0><<<grid, 128>>>(x, A);
    affinity_kernel<1><<<grid, 128>>>(x, A);
}